// round 3
// baseline (speedup 1.0000x reference)
#include <cuda_runtime.h>
#include <math.h>
#include <float.h>

#define B    64
#define H    224
#define W    224
#define HW   (H*W)
#define NTOT (B*HW)
#define NC   196
#define NBR  10
#define WINS 20
#define ITERS 50

#define TILE 32
#define HALO 8              // supports 8 ITERATIONS (erosion = 1 ring/iteration)
#define REG  48
#define RPX  (REG*REG)      // 2304
#define TPB  256            // 16x16 chunks of 3x3 px

// ---------------- scratch (static device globals) ---------------------------
__device__ float         g_gray[NTOT];
__device__ float         g_wgm [NTOT];
__device__ float         g_wcd [4][NTOT];     // wgm + 10*cdiff[d]
__device__ float         g_dist[2][NTOT];
__device__ unsigned char g_mask[2][NTOT];
__device__ int           g_centi[B*NC*2];

// ---------------- phase 1: gray ----------------------------------------------
__global__ void k_gray(const float* __restrict__ x) {
    int i = blockIdx.x * blockDim.x + threadIdx.x;
    if (i >= NTOT) return;
    int b = i / HW;
    int r = i - b * HW;
    const float* xb = x + (size_t)b * 3 * HW;
    float R = xb[r], G = xb[HW + r], Bv = xb[2 * HW + r];
    float t = __fadd_rn(__fmul_rn(0.2989f, R), __fmul_rn(0.587f, G));
    g_gray[i] = __fadd_rn(t, __fmul_rn(0.114f, Bv));
}

// ---------------- phase 1: sobel -> grad + wgm -------------------------------
__device__ __forceinline__ float grayAt(const float* gb, int y, int x) {
    if ((unsigned)y >= (unsigned)H || (unsigned)x >= (unsigned)W) return 0.0f;
    return gb[y * W + x];
}

__global__ void k_grad(float* __restrict__ out_grad) {
    int i = blockIdx.x * blockDim.x + threadIdx.x;
    if (i >= NTOT) return;
    int b = i / HW;
    int r = i - b * HW;
    int y = r / W, x = r - y * W;
    const float* gb = g_gray + b * HW;

    float a00 = grayAt(gb, y - 1, x - 1), a01 = grayAt(gb, y - 1, x), a02 = grayAt(gb, y - 1, x + 1);
    float a10 = grayAt(gb, y,     x - 1),                             a12 = grayAt(gb, y,     x + 1);
    float a20 = grayAt(gb, y + 1, x - 1), a21 = grayAt(gb, y + 1, x), a22 = grayAt(gb, y + 1, x + 1);

    float gx = __fadd_rn(-a00, a02);
    gx = __fadd_rn(gx, __fmul_rn(-2.0f, a10));
    gx = __fadd_rn(gx, __fmul_rn( 2.0f, a12));
    gx = __fadd_rn(gx, -a20);
    gx = __fadd_rn(gx,  a22);
    float gy = __fadd_rn(-a00, __fmul_rn(-2.0f, a01));
    gy = __fadd_rn(gy, -a02);
    gy = __fadd_rn(gy,  a20);
    gy = __fadd_rn(gy, __fmul_rn(2.0f, a21));
    gy = __fadd_rn(gy,  a22);

    float s = __fadd_rn(__fadd_rn(__fmul_rn(gx, gx), __fmul_rn(gy, gy)), 1e-8f);
    float g = sqrtf(s);
    out_grad[i] = g;
    g_wgm[i] = __fmul_rn(powf(g, 4.0f), 10.0f);
}

// ---------------- phase 1: fused cost maps wcd[d] = wgm + 10*cdiff[d] --------
__global__ void k_wcd(const float* __restrict__ x) {
    int i = blockIdx.x * blockDim.x + threadIdx.x;
    if (i >= NTOT) return;
    int b = i / HW;
    int r = i - b * HW;
    int y = r / W, xx = r - y * W;
    const float* xb = x + (size_t)b * 3 * HW;

    float c0 = xb[r], c1 = xb[HW + r], c2 = xb[2 * HW + r];
    int yp = (y + 1 == H) ? 0 : y + 1;
    int ym = (y == 0) ? H - 1 : y - 1;
    int xp = (xx + 1 == W) ? 0 : xx + 1;
    int xm = (xx == 0) ? W - 1 : xx - 1;
    int nb[4];
    nb[0] = yp * W + xx;
    nb[1] = ym * W + xx;
    nb[2] = y  * W + xp;
    nb[3] = y  * W + xm;
    float w = g_wgm[i];
#pragma unroll
    for (int d = 0; d < 4; d++) {
        int n = nb[d];
        float s = __fadd_rn(__fadd_rn(fabsf(c0 - xb[n]), fabsf(c1 - xb[HW + n])),
                            fabsf(c2 - xb[2 * HW + n]));
        g_wcd[d][i] = __fadd_rn(w, __fmul_rn(s, 10.0f));
    }
}

// ---------------- phase 2: nearest-minima snap ------------------------------
#define OCCW ((HW + 31) / 32)

__device__ __forceinline__ float wredminf(float v) {
#pragma unroll
    for (int o = 16; o; o >>= 1) v = fminf(v, __shfl_xor_sync(0xffffffffu, v, o));
    return v;
}
__device__ __forceinline__ int wredmini(int v) {
#pragma unroll
    for (int o = 16; o; o >>= 1) v = min(v, __shfl_xor_sync(0xffffffffu, v, o));
    return v;
}

__global__ void k_cents(const float* __restrict__ grad, float* __restrict__ cents_out) {
    extern __shared__ unsigned char smraw[];
    float*        sg  = (float*)smraw;
    unsigned int* occ = (unsigned int*)(smraw + (size_t)HW * sizeof(float));
    __shared__ float smv[NC];
    __shared__ int   sli[NC];

    int b = blockIdx.x;
    int tid = threadIdx.x;
    const float* gb = grad + b * HW;
    for (int i = tid; i < HW; i += TPB) sg[i] = gb[i];
    for (int i = tid; i < OCCW; i += TPB) occ[i] = 0u;
    __syncthreads();

    int warp = tid >> 5, lane = tid & 31;
    // Phase A: per-window min value + first (raster-order) min index, occ-blind
    for (int k = warp; k < NC; k += 8) {
        int cy = 8 + 16 * (k / 14);
        int cx = 8 + 16 * (k % 14);
        int ymin = max(0, cy - NBR), ymax = min(H, cy + NBR);
        int xmin = max(0, cx - NBR), xmax = min(W, cx + NBR);
        int h = ymax - ymin, w = xmax - xmin;

        float colmin = INFINITY;
        bool lv = (lane < w) && (lane < WINS);
        if (lv) {
            const float* col = sg + ymin * W + xmin + lane;
#pragma unroll
            for (int wy = 0; wy < WINS; wy++) {
                if (wy < h) colmin = fminf(colmin, col[wy * W]);
            }
        }
        float mv = wredminf(colmin);
        int li = WINS * WINS;
        if (lv) {
            const float* col = sg + ymin * W + xmin + lane;
#pragma unroll
            for (int wy = 0; wy < WINS; wy++) {
                if (wy < h && col[wy * W] == mv) { li = wy * WINS + lane; break; }
            }
        }
        li = wredmini(li);
        if (lane == 0) { smv[k] = mv; sli[k] = li; }
    }
    __syncthreads();

    // Phase B: serial resolve honoring occupancy (rare conflicts rescanned)
    if (tid == 0) {
        for (int k = 0; k < NC; k++) {
            int cy = 8 + 16 * (k / 14);
            int cx = 8 + 16 * (k % 14);
            int ymin = max(0, cy - NBR), ymax = min(H, cy + NBR);
            int xmin = max(0, cx - NBR), xmax = min(W, cx + NBR);
            int h = ymax - ymin, w = xmax - xmin;
            int ny = cy, nx = cx;
            bool found = false;
            int li = sli[k];
            float mv = smv[k];
            if (li < WINS * WINS) {
                int py = ymin + li / WINS, px = xmin + li % WINS;
                int bi = py * W + px;
                if (!((occ[bi >> 5] >> (bi & 31)) & 1u)) {
                    ny = py; nx = px; found = true;
                } else {
                    for (int l2 = 0; l2 < WINS * WINS; l2++) {
                        int wy = l2 / WINS, wx = l2 % WINS;
                        if (wy < h && wx < w) {
                            int b2 = (ymin + wy) * W + (xmin + wx);
                            if (sg[b2] == mv && !((occ[b2 >> 5] >> (b2 & 31)) & 1u)) {
                                ny = ymin + wy; nx = xmin + wx; found = true; break;
                            }
                        }
                    }
                }
            }
            if (found) {
                int bi = ny * W + nx;
                occ[bi >> 5] |= (1u << (bi & 31));
            }
            cents_out[(b * NC + k) * 2 + 0] = (float)ny;
            cents_out[(b * NC + k) * 2 + 1] = (float)nx;
            g_centi[(b * NC + k) * 2 + 0] = ny;
            g_centi[(b * NC + k) * 2 + 1] = nx;
        }
    }
}

// ---------------- phase 3: init + scatter ------------------------------------
__global__ void k_init() {
    int i = blockIdx.x * blockDim.x + threadIdx.x;
    if (i >= NTOT) return;
    g_dist[0][i] = INFINITY;
    g_mask[0][i] = 255;
}

__global__ void k_scatter() {
    int b = threadIdx.x;
    if (b >= B) return;
    for (int k = 0; k < NC; k++) {
        int ny = g_centi[(b * NC + k) * 2 + 0];
        int nx = g_centi[(b * NC + k) * 2 + 1];
        int idx = b * HW + ny * W + nx;
        g_dist[0][idx] = 0.0f;
        g_mask[0][idx] = (unsigned char)k;
    }
}

// ---------------- phase 3: register-chunk propagation, up to 8 iters/kernel --
__global__ __launch_bounds__(TPB, 2) void k_prop(int s, int niter) {
    __shared__ float         sD[RPX];
    __shared__ unsigned char sM[RPX];
    __shared__ float         cD1[TPB]; __shared__ unsigned char cM1[TPB]; // px(2,0) after pass1
    __shared__ float         cD2[TPB]; __shared__ unsigned char cM2[TPB]; // px(0,2) after pass3

    const int tid = threadIdx.x;
    const int b  = blockIdx.z;
    const int oy = blockIdx.y * TILE;
    const int ox = blockIdx.x * TILE;

    const float*         dIn = g_dist[s];
    const unsigned char* mIn = g_mask[s];

    // coalesced load of dist/mask region (torus wrap in halo)
    for (int idx = tid; idx < RPX; idx += TPB) {
        int ly = idx / REG, lx = idx - ly * REG;
        int gy = oy - HALO + ly; gy += (gy < 0) ? H : 0; gy -= (gy >= H) ? H : 0;
        int gx = ox - HALO + lx; gx += (gx < 0) ? W : 0; gx -= (gx >= W) ? W : 0;
        int gi = b * HW + gy * W + gx;
        sD[idx] = dIn[gi];
        sM[idx] = mIn[gi];
    }
    __syncthreads();

    const int ccy = tid >> 4, ccx = tid & 15;
    const int by = ccy * 3, bx = ccx * 3;
    const int base = by * REG + bx;

    float d[3][3]; int m[3][3]; float wc[4][3][3];
#pragma unroll
    for (int i = 0; i < 3; i++)
#pragma unroll
        for (int j = 0; j < 3; j++) {
            int idx = base + i * REG + j;
            d[i][j] = sD[idx];
            m[i][j] = sM[idx];
        }
#pragma unroll
    for (int i = 0; i < 3; i++)
#pragma unroll
        for (int j = 0; j < 3; j++) {
            int ly = by + i, lx = bx + j;
            int gy = oy - HALO + ly; gy += (gy < 0) ? H : 0; gy -= (gy >= H) ? H : 0;
            int gx = ox - HALO + lx; gx += (gx < 0) ? W : 0; gx -= (gx >= W) ? W : 0;
            int gi = b * HW + gy * W + gx;
            wc[0][i][j] = g_wcd[0][gi];
            wc[1][i][j] = g_wcd[1][gi];
            wc[2][i][j] = g_wcd[2][gi];
            wc[3][i][j] = g_wcd[3][gi];
        }
    // init corner2 (read by pass 0 before pass 3 ever writes it)
    cD2[tid] = d[0][2]; cM2[tid] = (unsigned char)m[0][2];
    __syncthreads();

#pragma unroll 1
    for (int it = 0; it < niter; it++) {
        // ---- pass 0 (dir (-1,0)): read y+1; update rows ascending; publish row 2
        {
            float e0, e1, e2; int f0, f1, f2;
            if (by + 3 < REG) {
                int xo = (by + 3) * REG + bx;
                e0 = sD[xo]; e1 = sD[xo + 1]; e2 = cD2[tid + 16];
                f0 = sM[xo]; f1 = sM[xo + 1]; f2 = cM2[tid + 16];
            } else { e0 = e1 = e2 = INFINITY; f0 = f1 = f2 = 0; }
#pragma unroll
            for (int i = 0; i < 3; i++) {
                float n0, n1, n2; int q0, q1, q2;
                if (i < 2) { n0 = d[i+1][0]; n1 = d[i+1][1]; n2 = d[i+1][2];
                             q0 = m[i+1][0]; q1 = m[i+1][1]; q2 = m[i+1][2]; }
                else       { n0 = e0; n1 = e1; n2 = e2; q0 = f0; q1 = f1; q2 = f2; }
                float w0 = __fadd_rn(n0, wc[0][i][0]); if (w0 < d[i][0]) { d[i][0] = w0; m[i][0] = q0; }
                float w1 = __fadd_rn(n1, wc[0][i][1]); if (w1 < d[i][1]) { d[i][1] = w1; m[i][1] = q1; }
                float w2 = __fadd_rn(n2, wc[0][i][2]); if (w2 < d[i][2]) { d[i][2] = w2; m[i][2] = q2; }
            }
            int xw = (by + 2) * REG + bx;
            sD[xw] = d[2][0]; sD[xw+1] = d[2][1]; sD[xw+2] = d[2][2];
            sM[xw] = (unsigned char)m[2][0]; sM[xw+1] = (unsigned char)m[2][1]; sM[xw+2] = (unsigned char)m[2][2];
            __syncthreads();
        }
        // ---- pass 1 (dir (1,0)): read y-1; rows descending; publish (0,0),(1,0)+corner1(2,0)
        {
            float e0, e1, e2; int f0, f1, f2;
            if (by > 0) {
                int xo = (by - 1) * REG + bx;
                e0 = sD[xo]; e1 = sD[xo + 1]; e2 = sD[xo + 2];
                f0 = sM[xo]; f1 = sM[xo + 1]; f2 = sM[xo + 2];
            } else { e0 = e1 = e2 = INFINITY; f0 = f1 = f2 = 0; }
#pragma unroll
            for (int ii = 0; ii < 3; ii++) {
                int i = 2 - ii;
                float n0, n1, n2; int q0, q1, q2;
                if (i > 0) { n0 = d[i-1][0]; n1 = d[i-1][1]; n2 = d[i-1][2];
                             q0 = m[i-1][0]; q1 = m[i-1][1]; q2 = m[i-1][2]; }
                else       { n0 = e0; n1 = e1; n2 = e2; q0 = f0; q1 = f1; q2 = f2; }
                float w0 = __fadd_rn(n0, wc[1][i][0]); if (w0 < d[i][0]) { d[i][0] = w0; m[i][0] = q0; }
                float w1 = __fadd_rn(n1, wc[1][i][1]); if (w1 < d[i][1]) { d[i][1] = w1; m[i][1] = q1; }
                float w2 = __fadd_rn(n2, wc[1][i][2]); if (w2 < d[i][2]) { d[i][2] = w2; m[i][2] = q2; }
            }
            sD[base] = d[0][0];       sM[base] = (unsigned char)m[0][0];
            sD[base + REG] = d[1][0]; sM[base + REG] = (unsigned char)m[1][0];
            cD1[tid] = d[2][0];       cM1[tid] = (unsigned char)m[2][0];
            __syncthreads();
        }
        // ---- pass 2 (dir (0,-1)): read x+1; cols ascending; publish col 2
        {
            float e0, e1, e2; int f0, f1, f2;
            if (bx + 3 < REG) {
                e0 = sD[base + 3]; e1 = sD[base + REG + 3]; e2 = cD1[tid + 1];
                f0 = sM[base + 3]; f1 = sM[base + REG + 3]; f2 = cM1[tid + 1];
            } else { e0 = e1 = e2 = INFINITY; f0 = f1 = f2 = 0; }
#pragma unroll
            for (int j = 0; j < 3; j++) {
                float n0, n1, n2; int q0, q1, q2;
                if (j < 2) { n0 = d[0][j+1]; n1 = d[1][j+1]; n2 = d[2][j+1];
                             q0 = m[0][j+1]; q1 = m[1][j+1]; q2 = m[2][j+1]; }
                else       { n0 = e0; n1 = e1; n2 = e2; q0 = f0; q1 = f1; q2 = f2; }
                float w0 = __fadd_rn(n0, wc[2][0][j]); if (w0 < d[0][j]) { d[0][j] = w0; m[0][j] = q0; }
                float w1 = __fadd_rn(n1, wc[2][1][j]); if (w1 < d[1][j]) { d[1][j] = w1; m[1][j] = q1; }
                float w2 = __fadd_rn(n2, wc[2][2][j]); if (w2 < d[2][j]) { d[2][j] = w2; m[2][j] = q2; }
            }
            sD[base + 2] = d[0][2];           sM[base + 2] = (unsigned char)m[0][2];
            sD[base + REG + 2] = d[1][2];     sM[base + REG + 2] = (unsigned char)m[1][2];
            sD[base + 2 * REG + 2] = d[2][2]; sM[base + 2 * REG + 2] = (unsigned char)m[2][2];
            __syncthreads();
        }
        // ---- pass 3 (dir (0,1)): read x-1; cols descending; publish (0,0),(0,1)+corner2(0,2)
        {
            float e0, e1, e2; int f0, f1, f2;
            if (bx > 0) {
                e0 = sD[base - 1]; e1 = sD[base + REG - 1]; e2 = sD[base + 2 * REG - 1];
                f0 = sM[base - 1]; f1 = sM[base + REG - 1]; f2 = sM[base + 2 * REG - 1];
            } else { e0 = e1 = e2 = INFINITY; f0 = f1 = f2 = 0; }
#pragma unroll
            for (int jj = 0; jj < 3; jj++) {
                int j = 2 - jj;
                float n0, n1, n2; int q0, q1, q2;
                if (j > 0) { n0 = d[0][j-1]; n1 = d[1][j-1]; n2 = d[2][j-1];
                             q0 = m[0][j-1]; q1 = m[1][j-1]; q2 = m[2][j-1]; }
                else       { n0 = e0; n1 = e1; n2 = e2; q0 = f0; q1 = f1; q2 = f2; }
                float w0 = __fadd_rn(n0, wc[3][0][j]); if (w0 < d[0][j]) { d[0][j] = w0; m[0][j] = q0; }
                float w1 = __fadd_rn(n1, wc[3][1][j]); if (w1 < d[1][j]) { d[1][j] = w1; m[1][j] = q1; }
                float w2 = __fadd_rn(n2, wc[3][2][j]); if (w2 < d[2][j]) { d[2][j] = w2; m[2][j] = q2; }
            }
            sD[base] = d[0][0];     sM[base] = (unsigned char)m[0][0];
            sD[base + 1] = d[0][1]; sM[base + 1] = (unsigned char)m[0][1];
            cD2[tid] = d[0][2];     cM2[tid] = (unsigned char)m[0][2];
            __syncthreads();
        }
    }

    // dump regs to smem, then coalesced store of central tile
#pragma unroll
    for (int i = 0; i < 3; i++)
#pragma unroll
        for (int j = 0; j < 3; j++) {
            int idx = base + i * REG + j;
            sD[idx] = d[i][j];
            sM[idx] = (unsigned char)m[i][j];
        }
    __syncthreads();

    float*         dOut = g_dist[s ^ 1];
    unsigned char* mOut = g_mask[s ^ 1];
    for (int idx = tid; idx < RPX; idx += TPB) {
        int ly = idx / REG, lx = idx - ly * REG;
        if (ly >= HALO && ly < HALO + TILE && lx >= HALO && lx < HALO + TILE) {
            int gi = b * HW + (oy - HALO + ly) * W + (ox - HALO + lx);
            dOut[gi] = sD[idx];
            mOut[gi] = sM[idx];
        }
    }
}

// ---------------- final: mask -> float output --------------------------------
__global__ void k_final(int s, float* __restrict__ out_mask) {
    int i = blockIdx.x * blockDim.x + threadIdx.x;
    if (i >= NTOT) return;
    unsigned char m = g_mask[s][i];
    out_mask[i] = (m == 255) ? -1.0f : (float)m;
}

// ---------------- launch ------------------------------------------------------
extern "C" void kernel_launch(void* const* d_in, const int* in_sizes, int n_in,
                              void* d_out, int out_size) {
    const float* x = (const float*)d_in[0];
    float* out = (float*)d_out;
    float* out_grad  = out;                       // (B,1,H,W)
    float* out_cents = out + NTOT;                // (B,196,2)
    float* out_mask  = out + NTOT + B * NC * 2;   // (B,H,W)

    const int T = 256;
    const int G = (NTOT + T - 1) / T;

    static const size_t centsSmem = (size_t)HW * sizeof(float) + (size_t)OCCW * sizeof(unsigned int);
    cudaFuncSetAttribute(k_cents, cudaFuncAttributeMaxDynamicSharedMemorySize, (int)centsSmem);

    k_gray <<<G, T>>>(x);
    k_grad <<<G, T>>>(out_grad);
    k_wcd  <<<G, T>>>(x);
    k_cents<<<B, TPB, centsSmem>>>(out_grad, out_cents);
    k_init <<<G, T>>>();
    k_scatter<<<1, 64>>>();

    dim3 pg(W / TILE, H / TILE, B);
    int s = 0;
    int remaining = ITERS;
    while (remaining > 0) {
        int it = remaining >= HALO ? HALO : remaining;
        k_prop<<<pg, TPB>>>(s, it);
        s ^= 1;
        remaining -= it;
    }
    k_final<<<G, T>>>(s, out_mask);
}